// round 1
// baseline (speedup 1.0000x reference)
#include <cuda_runtime.h>

// ---------------------------------------------------------------------------
// LaneAttention: per-lane MLP score -> per-group(8) softmax -> weighted pool
// M = 262144 lanes, groups of exactly 8 contiguous lanes (seg sorted), N=32768
// out[g][0:192] = sum_{j=0..7} prob[8g+j] * concat(ht, info, fut)[8g+j][:]
// ---------------------------------------------------------------------------

static constexpr int TPB      = 256;   // threads per block = lanes per block
static constexpr int XSTRIDE  = 132;   // smem row stride (floats): 16B aligned, 4*lane bank offset
static constexpr int GROUPS_PER_BLOCK = TPB / 8;   // 32

__device__ __forceinline__ unsigned long long pack_dup(float x) {
    unsigned long long r;
    asm("mov.b64 %0, {%1, %1};" : "=l"(r) : "f"(x));
    return r;
}
__device__ __forceinline__ unsigned long long pack_xy(float x, float y) {
    unsigned long long r;
    asm("mov.b64 %0, {%1, %2};" : "=l"(r) : "f"(x), "f"(y));
    return r;
}
__device__ __forceinline__ void ffma2(unsigned long long &d, unsigned long long a, unsigned long long b) {
    // packed f32x2 fma: d = a*b + d  (2 FMAs per instruction; ptxas never auto-fuses this)
    asm("fma.rn.f32x2 %0, %1, %2, %0;" : "+l"(d) : "l"(a), "l"(b));
}
__device__ __forceinline__ float2 unpack2(unsigned long long v) {
    float2 f;
    asm("mov.b64 {%0, %1}, %2;" : "=f"(f.x), "=f"(f.y) : "l"(v));
    return f;
}

extern __shared__ float smem_f[];

__global__ __launch_bounds__(TPB, 1)
void lane_attn_kernel(const float* __restrict__ ht,
                      const float* __restrict__ info,
                      const float* __restrict__ fut,
                      const float* __restrict__ W1,   // [128,16] row-major
                      const float* __restrict__ b1,   // [16]
                      const float* __restrict__ W2,   // [16]
                      const float* __restrict__ b2,   // [1]
                      const int*   __restrict__ seg,  // [M]
                      float* __restrict__ out)        // [N,192]
{
    // smem layout
    float* xsh   = smem_f;                       // 256 * 132 floats
    float* w1s   = xsh + TPB * XSTRIDE;          // 2048 floats (128x16), 16B aligned
    float* probs = w1s + 128 * 16;               // 256 floats
    int*   outrow = (int*)(probs + TPB);         // 32 ints

    const int tid = threadIdx.x;

    // stage W1 into smem (coalesced, 8 floats per thread)
    #pragma unroll
    for (int i = 0; i < 8; ++i)
        w1s[tid + i * 256] = W1[tid + i * 256];
    __syncthreads();

    const int lane = blockIdx.x * TPB + tid;

    // --- Phase 1: per-lane MLP score, x stashed into smem ------------------
    unsigned long long hp[8];
    {
        const float2* b12 = (const float2*)b1;
        #pragma unroll
        for (int j = 0; j < 8; ++j) {
            float2 bv = b12[j];
            hp[j] = pack_xy(bv.x, bv.y);
        }
    }

    float* xrow = xsh + tid * XSTRIDE;
    const float4* ht4 = (const float4*)(ht   + (size_t)lane * 64);
    const float4* in4 = (const float4*)(info + (size_t)lane * 64);

    // ht part: k = 0..63
    #pragma unroll 8
    for (int q = 0; q < 16; ++q) {
        float4 v = ht4[q];
        ((float4*)xrow)[q] = v;                 // stash (STS.128, 4-way conflict, cheap)
        float xs[4] = {v.x, v.y, v.z, v.w};
        #pragma unroll
        for (int c = 0; c < 4; ++c) {
            unsigned long long xv = pack_dup(xs[c]);
            const double2* wr = (const double2*)(w1s + (q * 4 + c) * 16);
            double2 w01 = wr[0];                // pairs (j0,j1),(j2,j3)  LDS.128 broadcast
            double2 w23 = wr[1];                // pairs (j4,j5),(j6,j7)
            ffma2(hp[0], xv, __double_as_longlong(w01.x));
            ffma2(hp[1], xv, __double_as_longlong(w01.y));
            ffma2(hp[2], xv, __double_as_longlong(w23.x));
            ffma2(hp[3], xv, __double_as_longlong(w23.y));
            const double2* wr2 = wr + 2;
            double2 w45 = wr2[0];
            double2 w67 = wr2[1];
            ffma2(hp[4], xv, __double_as_longlong(w45.x));
            ffma2(hp[5], xv, __double_as_longlong(w45.y));
            ffma2(hp[6], xv, __double_as_longlong(w67.x));
            ffma2(hp[7], xv, __double_as_longlong(w67.y));
        }
    }
    // info part: k = 64..127
    #pragma unroll 8
    for (int q = 0; q < 16; ++q) {
        float4 v = in4[q];
        ((float4*)xrow)[16 + q] = v;
        float xs[4] = {v.x, v.y, v.z, v.w};
        #pragma unroll
        for (int c = 0; c < 4; ++c) {
            unsigned long long xv = pack_dup(xs[c]);
            const double2* wr = (const double2*)(w1s + ((16 + q) * 4 + c) * 16);
            double2 w01 = wr[0];
            double2 w23 = wr[1];
            ffma2(hp[0], xv, __double_as_longlong(w01.x));
            ffma2(hp[1], xv, __double_as_longlong(w01.y));
            ffma2(hp[2], xv, __double_as_longlong(w23.x));
            ffma2(hp[3], xv, __double_as_longlong(w23.y));
            const double2* wr2 = wr + 2;
            double2 w45 = wr2[0];
            double2 w67 = wr2[1];
            ffma2(hp[4], xv, __double_as_longlong(w45.x));
            ffma2(hp[5], xv, __double_as_longlong(w45.y));
            ffma2(hp[6], xv, __double_as_longlong(w67.x));
            ffma2(hp[7], xv, __double_as_longlong(w67.y));
        }
    }

    // ReLU + second layer -> score
    float score = b2[0];
    #pragma unroll
    for (int j = 0; j < 8; ++j) {
        float2 h2 = unpack2(hp[j]);
        score += fmaxf(h2.x, 0.f) * W2[2 * j]
               + fmaxf(h2.y, 0.f) * W2[2 * j + 1];
    }

    // --- group-of-8 softmax via shuffles (groups are warp-aligned) ---------
    float m = score;
    #pragma unroll
    for (int d = 1; d < 8; d <<= 1)
        m = fmaxf(m, __shfl_xor_sync(0xffffffffu, m, d));
    float e = __expf(score - m);
    float s = e;
    #pragma unroll
    for (int d = 1; d < 8; d <<= 1)
        s += __shfl_xor_sync(0xffffffffu, s, d);
    probs[tid] = e / s;

    if ((tid & 7) == 0)
        outrow[tid >> 3] = seg[lane];

    __syncthreads();

    // --- Phase 2: warp-per-group weighted pooling ---------------------------
    const int wrp = tid >> 5;
    const int lt  = tid & 31;
    #pragma unroll
    for (int gi = 0; gi < 4; ++gi) {
        const int gloc  = wrp * 4 + gi;          // local group 0..31
        const int lbase = gloc * 8;              // local lane base
        const size_t gbase = (size_t)(blockIdx.x * TPB + lbase) * 64;

        float a0 = 0.f, a1 = 0.f, a2 = 0.f, a3 = 0.f, a4 = 0.f, a5 = 0.f;
        #pragma unroll
        for (int j = 0; j < 8; ++j) {
            const float pj = probs[lbase + j];           // broadcast
            const float* xr = xsh + (lbase + j) * XSTRIDE;
            a0 += pj * xr[lt];                           // ht  cols 0..31
            a1 += pj * xr[lt + 32];                      // ht  cols 32..63
            a2 += pj * xr[lt + 64];                      // info cols 0..31
            a3 += pj * xr[lt + 96];                      // info cols 32..63
            const float* fr = fut + gbase + (size_t)j * 64;
            a4 += pj * fr[lt];                           // fut cols 0..31
            a5 += pj * fr[lt + 32];                      // fut cols 32..63
        }
        float* o = out + (size_t)outrow[gloc] * 192;
        o[lt]       = a0;
        o[lt + 32]  = a1;
        o[lt + 64]  = a2;
        o[lt + 96]  = a3;
        o[lt + 128] = a4;
        o[lt + 160] = a5;
    }
}

extern "C" void kernel_launch(void* const* d_in, const int* in_sizes, int n_in,
                              void* d_out, int out_size)
{
    const float* ht   = (const float*)d_in[0];
    const float* info = (const float*)d_in[1];
    const float* fut  = (const float*)d_in[2];
    const float* W1   = (const float*)d_in[3];
    const float* b1   = (const float*)d_in[4];
    const float* W2   = (const float*)d_in[5];
    const float* b2   = (const float*)d_in[6];
    const int*   seg  = (const int*)d_in[7];
    float* out = (float*)d_out;

    const int M = in_sizes[0] / 64;          // 262144
    const int nblocks = M / TPB;             // 1024

    const int smem_bytes = (TPB * XSTRIDE + 128 * 16 + TPB) * (int)sizeof(float)
                         + GROUPS_PER_BLOCK * (int)sizeof(int);   // 144512 B

    static bool attr_set = false;            // idempotent host-side attribute, not a stream op
    if (!attr_set) {
        cudaFuncSetAttribute(lane_attn_kernel,
                             cudaFuncAttributeMaxDynamicSharedMemorySize, smem_bytes);
        attr_set = true;
    }

    lane_attn_kernel<<<nblocks, TPB, smem_bytes>>>(ht, info, fut, W1, b1, W2, b2, seg, out);
}

// round 2
// speedup vs baseline: 1.0452x; 1.0452x over previous
#include <cuda_runtime.h>

// ---------------------------------------------------------------------------
// LaneAttention: per-lane MLP score -> per-group(8) softmax -> weighted pool
// M = 262144 lanes, groups of exactly 8 contiguous lanes (seg sorted), N=32768
// out[g][0:192] = sum_{j=0..7} prob[8g+j] * concat(ht, info, fut)[8g+j][:]
//
// R2: no smem x-stash. Phase 2 re-reads ht/info from global (L2 hits — the
// block just streamed them in phase 1). Small static smem -> high occupancy.
// ---------------------------------------------------------------------------

static constexpr int TPB = 256;                 // threads per block = lanes per block
static constexpr int GROUPS_PER_BLOCK = TPB / 8;

__device__ __forceinline__ unsigned long long pack_dup(float x) {
    unsigned long long r;
    asm("mov.b64 %0, {%1, %1};" : "=l"(r) : "f"(x));
    return r;
}
__device__ __forceinline__ unsigned long long pack_xy(float x, float y) {
    unsigned long long r;
    asm("mov.b64 %0, {%1, %2};" : "=l"(r) : "f"(x), "f"(y));
    return r;
}
__device__ __forceinline__ void ffma2(unsigned long long &d, unsigned long long a, unsigned long long b) {
    // packed f32x2 fma: d = a*b + d  (2 FMAs/instr; ptxas never auto-fuses this)
    asm("fma.rn.f32x2 %0, %1, %2, %0;" : "+l"(d) : "l"(a), "l"(b));
}
__device__ __forceinline__ float2 unpack2(unsigned long long v) {
    float2 f;
    asm("mov.b64 {%0, %1}, %2;" : "=f"(f.x), "=f"(f.y) : "l"(v));
    return f;
}

__global__ __launch_bounds__(TPB)
void lane_attn_kernel(const float* __restrict__ ht,
                      const float* __restrict__ info,
                      const float* __restrict__ fut,
                      const float* __restrict__ W1,   // [128,16] row-major
                      const float* __restrict__ b1,   // [16]
                      const float* __restrict__ W2,   // [16]
                      const float* __restrict__ b2,   // [1]
                      const int*   __restrict__ seg,  // [M]
                      float* __restrict__ out)        // [N,192]
{
    __shared__ float w1s[128 * 16];      // 8 KB
    __shared__ float probs[TPB];
    __shared__ int   outrow[GROUPS_PER_BLOCK];

    const int tid = threadIdx.x;

    // stage W1 into smem (coalesced, 8 floats per thread)
    #pragma unroll
    for (int i = 0; i < 8; ++i)
        w1s[tid + i * 256] = W1[tid + i * 256];
    __syncthreads();

    const int lane = blockIdx.x * TPB + tid;

    // --- Phase 1: per-lane MLP score (packed f32x2 FMAs, uniform LDS.128) ---
    unsigned long long hp[8];
    {
        const float2* b12 = (const float2*)b1;
        #pragma unroll
        for (int j = 0; j < 8; ++j) {
            float2 bv = b12[j];
            hp[j] = pack_xy(bv.x, bv.y);
        }
    }

    const float4* ht4 = (const float4*)(ht   + (size_t)lane * 64);
    const float4* in4 = (const float4*)(info + (size_t)lane * 64);

    #pragma unroll 4
    for (int q = 0; q < 16; ++q) {
        float4 v = ht4[q];
        float xs[4] = {v.x, v.y, v.z, v.w};
        #pragma unroll
        for (int c = 0; c < 4; ++c) {
            unsigned long long xv = pack_dup(xs[c]);
            const double2* wr = (const double2*)(w1s + (q * 4 + c) * 16);
            double2 w01 = wr[0];   // weight pairs (j0,j1),(j2,j3) — warp-uniform LDS.128
            double2 w23 = wr[1];
            ffma2(hp[0], xv, __double_as_longlong(w01.x));
            ffma2(hp[1], xv, __double_as_longlong(w01.y));
            ffma2(hp[2], xv, __double_as_longlong(w23.x));
            ffma2(hp[3], xv, __double_as_longlong(w23.y));
            double2 w45 = wr[2];
            double2 w67 = wr[3];
            ffma2(hp[4], xv, __double_as_longlong(w45.x));
            ffma2(hp[5], xv, __double_as_longlong(w45.y));
            ffma2(hp[6], xv, __double_as_longlong(w67.x));
            ffma2(hp[7], xv, __double_as_longlong(w67.y));
        }
    }
    #pragma unroll 4
    for (int q = 0; q < 16; ++q) {
        float4 v = in4[q];
        float xs[4] = {v.x, v.y, v.z, v.w};
        #pragma unroll
        for (int c = 0; c < 4; ++c) {
            unsigned long long xv = pack_dup(xs[c]);
            const double2* wr = (const double2*)(w1s + ((16 + q) * 4 + c) * 16);
            double2 w01 = wr[0];
            double2 w23 = wr[1];
            ffma2(hp[0], xv, __double_as_longlong(w01.x));
            ffma2(hp[1], xv, __double_as_longlong(w01.y));
            ffma2(hp[2], xv, __double_as_longlong(w23.x));
            ffma2(hp[3], xv, __double_as_longlong(w23.y));
            double2 w45 = wr[2];
            double2 w67 = wr[3];
            ffma2(hp[4], xv, __double_as_longlong(w45.x));
            ffma2(hp[5], xv, __double_as_longlong(w45.y));
            ffma2(hp[6], xv, __double_as_longlong(w67.x));
            ffma2(hp[7], xv, __double_as_longlong(w67.y));
        }
    }

    // ReLU + second layer -> score
    float score = b2[0];
    #pragma unroll
    for (int j = 0; j < 8; ++j) {
        float2 h2 = unpack2(hp[j]);
        score += fmaxf(h2.x, 0.f) * W2[2 * j]
               + fmaxf(h2.y, 0.f) * W2[2 * j + 1];
    }

    // --- group-of-8 softmax via shuffles (groups are warp-aligned) ----------
    float m = score;
    #pragma unroll
    for (int d = 1; d < 8; d <<= 1)
        m = fmaxf(m, __shfl_xor_sync(0xffffffffu, m, d));
    float e = __expf(score - m);
    float s = e;
    #pragma unroll
    for (int d = 1; d < 8; d <<= 1)
        s += __shfl_xor_sync(0xffffffffu, s, d);
    probs[tid] = e / s;

    if ((tid & 7) == 0)
        outrow[tid >> 3] = seg[lane];

    __syncthreads();

    // --- Phase 2: warp-per-group weighted pooling (ht/info from L2) ---------
    const int wrp = tid >> 5;
    const int lt  = tid & 31;
    #pragma unroll
    for (int gi = 0; gi < 4; ++gi) {
        const int gloc  = wrp * 4 + gi;                       // local group 0..31
        const int lbase = gloc * 8;                           // local lane base
        const size_t grow = (size_t)(blockIdx.x * TPB + lbase) * 64;

        float a0 = 0.f, a1 = 0.f, a2 = 0.f, a3 = 0.f, a4 = 0.f, a5 = 0.f;
        #pragma unroll
        for (int j = 0; j < 8; ++j) {
            const float pj = probs[lbase + j];                // smem broadcast
            const float* hr = ht   + grow + (size_t)j * 64;   // L2 hit (just streamed)
            const float* ir = info + grow + (size_t)j * 64;   // L2 hit
            const float* fr = fut  + grow + (size_t)j * 64;   // DRAM (first touch)
            a0 += pj * hr[lt];
            a1 += pj * hr[lt + 32];
            a2 += pj * ir[lt];
            a3 += pj * ir[lt + 32];
            a4 += pj * fr[lt];
            a5 += pj * fr[lt + 32];
        }
        float* o = out + (size_t)outrow[gloc] * 192;
        o[lt]       = a0;
        o[lt + 32]  = a1;
        o[lt + 64]  = a2;
        o[lt + 96]  = a3;
        o[lt + 128] = a4;
        o[lt + 160] = a5;
    }
}

extern "C" void kernel_launch(void* const* d_in, const int* in_sizes, int n_in,
                              void* d_out, int out_size)
{
    const float* ht   = (const float*)d_in[0];
    const float* info = (const float*)d_in[1];
    const float* fut  = (const float*)d_in[2];
    const float* W1   = (const float*)d_in[3];
    const float* b1   = (const float*)d_in[4];
    const float* W2   = (const float*)d_in[5];
    const float* b2   = (const float*)d_in[6];
    const int*   seg  = (const int*)d_in[7];
    float* out = (float*)d_out;

    const int M = in_sizes[0] / 64;          // 262144
    const int nblocks = M / TPB;             // 1024

    lane_attn_kernel<<<nblocks, TPB>>>(ht, info, fut, W1, b1, W2, b2, seg, out);
}

// round 3
// speedup vs baseline: 1.3590x; 1.3003x over previous
#include <cuda_runtime.h>
#include <cstdint>

// ---------------------------------------------------------------------------
// LaneAttention: per-lane MLP score -> per-group(8) softmax -> weighted pool
// M = 262144 lanes, groups of 8 contiguous lanes, N = 32768, out [N,192]
//
// R3: phase-1 x reads staged through smem via cp.async (coalesced global,
// conflict-free padded smem), phase-2 vectorized to float4 (info half read
// from the resident smem stage). Weight reads stay as warp-uniform LDS.128.
// ---------------------------------------------------------------------------

static constexpr int TPB = 256;                 // threads = rows per block
static constexpr int XS  = 17;                  // smem row stride in float4 (16 data + 1 pad)

__device__ __forceinline__ unsigned long long pack_dup(float x) {
    unsigned long long r;
    asm("mov.b64 %0, {%1, %1};" : "=l"(r) : "f"(x));
    return r;
}
__device__ __forceinline__ unsigned long long pack_xy(float x, float y) {
    unsigned long long r;
    asm("mov.b64 %0, {%1, %2};" : "=l"(r) : "f"(x), "f"(y));
    return r;
}
__device__ __forceinline__ void ffma2(unsigned long long &d, unsigned long long a, unsigned long long b) {
    asm("fma.rn.f32x2 %0, %1, %2, %0;" : "+l"(d) : "l"(a), "l"(b));
}
__device__ __forceinline__ float2 unpack2(unsigned long long v) {
    float2 f;
    asm("mov.b64 {%0, %1}, %2;" : "=f"(f.x), "=f"(f.y) : "l"(v));
    return f;
}
__device__ __forceinline__ void cp_async16(uint32_t dst_smem, const void* src) {
    asm volatile("cp.async.cg.shared.global [%0], [%1], 16;\n"
                 :: "r"(dst_smem), "l"(src) : "memory");
}
__device__ __forceinline__ void cp_async_commit_wait() {
    asm volatile("cp.async.commit_group;\n");
    asm volatile("cp.async.wait_group 0;\n" ::: "memory");
}

extern __shared__ float smem_f[];

// dynamic smem layout (floats):
//   xbuf : 256 rows * 68 floats (17 float4, 1 pad)  = 17408
//   w1s  : 128*16                                   =  2048
//   probs: 256
//   outrow (int): 32
static constexpr int XBUF_F   = 256 * (XS * 4);      // 17408
static constexpr int SMEM_FLT = XBUF_F + 2048 + 256;
static constexpr int SMEM_BYTES = SMEM_FLT * 4 + 128;

__global__ __launch_bounds__(TPB)
void lane_attn_kernel(const float* __restrict__ ht,
                      const float* __restrict__ info,
                      const float* __restrict__ fut,
                      const float* __restrict__ W1,   // [128,16] row-major
                      const float* __restrict__ b1,   // [16]
                      const float* __restrict__ W2,   // [16]
                      const float* __restrict__ b2,   // [1]
                      const int*   __restrict__ seg,  // [M]
                      float* __restrict__ out)        // [N,192]
{
    float*  xbuf  = smem_f;
    float*  w1s   = smem_f + XBUF_F;
    float*  probs = w1s + 2048;
    int*    outrow = (int*)(probs + TPB);

    const int tid   = threadIdx.x;
    const int row0  = blockIdx.x * TPB;         // first global row of this block
    const uint32_t xbuf_s = (uint32_t)__cvta_generic_to_shared(xbuf);

    // stage W1 (coalesced) and group->output-row ids
    #pragma unroll
    for (int i = 0; i < 8; ++i)
        w1s[tid + i * 256] = W1[tid + i * 256];
    if (tid < 32)
        outrow[tid] = seg[row0 + tid * 8];

    // ---- stage A: ht rows [row0, row0+256) into xbuf (coalesced cp.async) --
    {
        const float4* src4 = (const float4*)(ht + (size_t)row0 * 64);
        #pragma unroll
        for (int u = 0; u < 16; ++u) {
            int f = tid + 256 * u;              // flat float4 idx 0..4095
            int r = f >> 4, c = f & 15;
            cp_async16(xbuf_s + (uint32_t)(r * XS + c) * 16u, src4 + f);
        }
        cp_async_commit_wait();
    }
    __syncthreads();

    // ---- phase 1a: MLP over ht half (k = 0..63) ----------------------------
    unsigned long long hp[8];
    {
        const float2* b12 = (const float2*)b1;
        #pragma unroll
        for (int j = 0; j < 8; ++j) {
            float2 bv = b12[j];
            hp[j] = pack_xy(bv.x, bv.y);
        }
    }

    const float4* xrow = ((const float4*)xbuf) + tid * XS;
    #pragma unroll 4
    for (int q = 0; q < 16; ++q) {
        float4 v = xrow[q];
        float xs[4] = {v.x, v.y, v.z, v.w};
        #pragma unroll
        for (int c = 0; c < 4; ++c) {
            unsigned long long xv = pack_dup(xs[c]);
            const double2* wr = (const double2*)(w1s + (q * 4 + c) * 16);
            double2 w01 = wr[0];
            double2 w23 = wr[1];
            ffma2(hp[0], xv, __double_as_longlong(w01.x));
            ffma2(hp[1], xv, __double_as_longlong(w01.y));
            ffma2(hp[2], xv, __double_as_longlong(w23.x));
            ffma2(hp[3], xv, __double_as_longlong(w23.y));
            double2 w45 = wr[2];
            double2 w67 = wr[3];
            ffma2(hp[4], xv, __double_as_longlong(w45.x));
            ffma2(hp[5], xv, __double_as_longlong(w45.y));
            ffma2(hp[6], xv, __double_as_longlong(w67.x));
            ffma2(hp[7], xv, __double_as_longlong(w67.y));
        }
    }
    __syncthreads();   // done reading stage A

    // ---- stage B: info rows into xbuf --------------------------------------
    {
        const float4* src4 = (const float4*)(info + (size_t)row0 * 64);
        #pragma unroll
        for (int u = 0; u < 16; ++u) {
            int f = tid + 256 * u;
            int r = f >> 4, c = f & 15;
            cp_async16(xbuf_s + (uint32_t)(r * XS + c) * 16u, src4 + f);
        }
        cp_async_commit_wait();
    }
    __syncthreads();

    // ---- phase 1b: MLP over info half (k = 64..127) -------------------------
    #pragma unroll 4
    for (int q = 0; q < 16; ++q) {
        float4 v = xrow[q];
        float xs[4] = {v.x, v.y, v.z, v.w};
        #pragma unroll
        for (int c = 0; c < 4; ++c) {
            unsigned long long xv = pack_dup(xs[c]);
            const double2* wr = (const double2*)(w1s + ((16 + q) * 4 + c) * 16);
            double2 w01 = wr[0];
            double2 w23 = wr[1];
            ffma2(hp[0], xv, __double_as_longlong(w01.x));
            ffma2(hp[1], xv, __double_as_longlong(w01.y));
            ffma2(hp[2], xv, __double_as_longlong(w23.x));
            ffma2(hp[3], xv, __double_as_longlong(w23.y));
            double2 w45 = wr[2];
            double2 w67 = wr[3];
            ffma2(hp[4], xv, __double_as_longlong(w45.x));
            ffma2(hp[5], xv, __double_as_longlong(w45.y));
            ffma2(hp[6], xv, __double_as_longlong(w67.x));
            ffma2(hp[7], xv, __double_as_longlong(w67.y));
        }
    }

    // ReLU + second layer -> score
    float score = b2[0];
    #pragma unroll
    for (int j = 0; j < 8; ++j) {
        float2 h2 = unpack2(hp[j]);
        score += fmaxf(h2.x, 0.f) * W2[2 * j]
               + fmaxf(h2.y, 0.f) * W2[2 * j + 1];
    }

    // ---- group-of-8 softmax (warp-aligned groups) ---------------------------
    float m = score;
    #pragma unroll
    for (int d = 1; d < 8; d <<= 1)
        m = fmaxf(m, __shfl_xor_sync(0xffffffffu, m, d));
    float e = __expf(score - m);
    float s = e;
    #pragma unroll
    for (int d = 1; d < 8; d <<= 1)
        s += __shfl_xor_sync(0xffffffffu, s, d);
    probs[tid] = e / s;

    __syncthreads();   // probs ready; xbuf (info) still resident

    // ---- phase 2: weighted pooling, float4 per lane -------------------------
    // warp covers 2 groups per iteration: lane = (h:1)(k:4), h selects group,
    // k selects float4 column 0..15 of each 64-float section.
    const int wrp = tid >> 5;
    const int h   = (tid >> 4) & 1;
    const int k   = tid & 15;
    const float4* xb4 = (const float4*)xbuf;

    #pragma unroll
    for (int it = 0; it < 2; ++it) {
        const int gloc  = wrp * 4 + it * 2 + h;          // local group 0..31
        const int lbase = gloc * 8;                      // local row base
        const float4* hb = (const float4*)(ht  + (size_t)(row0 + lbase) * 64);
        const float4* fb = (const float4*)(fut + (size_t)(row0 + lbase) * 64);
        const float4* ib = xb4 + lbase * XS;             // info from smem stage

        float4 ah = make_float4(0.f, 0.f, 0.f, 0.f);
        float4 ai = ah, af = ah;
        #pragma unroll
        for (int j = 0; j < 8; ++j) {
            const float p = probs[lbase + j];
            float4 hv = hb[j * 16 + k];
            float4 iv = ib[j * XS + k];
            float4 fv = fb[j * 16 + k];
            ah.x += p * hv.x; ah.y += p * hv.y; ah.z += p * hv.z; ah.w += p * hv.w;
            ai.x += p * iv.x; ai.y += p * iv.y; ai.z += p * iv.z; ai.w += p * iv.w;
            af.x += p * fv.x; af.y += p * fv.y; af.z += p * fv.z; af.w += p * fv.w;
        }
        float4* o4 = (float4*)(out + (size_t)outrow[gloc] * 192);
        o4[k]      = ah;
        o4[16 + k] = ai;
        o4[32 + k] = af;
    }
}

extern "C" void kernel_launch(void* const* d_in, const int* in_sizes, int n_in,
                              void* d_out, int out_size)
{
    const float* ht   = (const float*)d_in[0];
    const float* info = (const float*)d_in[1];
    const float* fut  = (const float*)d_in[2];
    const float* W1   = (const float*)d_in[3];
    const float* b1   = (const float*)d_in[4];
    const float* W2   = (const float*)d_in[5];
    const float* b2   = (const float*)d_in[6];
    const int*   seg  = (const int*)d_in[7];
    float* out = (float*)d_out;

    const int M = in_sizes[0] / 64;          // 262144
    const int nblocks = M / TPB;             // 1024

    static bool attr_set = false;
    if (!attr_set) {
        cudaFuncSetAttribute(lane_attn_kernel,
                             cudaFuncAttributeMaxDynamicSharedMemorySize, SMEM_BYTES);
        attr_set = true;
    }

    lane_attn_kernel<<<nblocks, TPB, SMEM_BYTES>>>(ht, info, fut, W1, b1, W2, b2, seg, out);
}

// round 4
// speedup vs baseline: 1.4800x; 1.0890x over previous
#include <cuda_runtime.h>
#include <cstdint>

// ---------------------------------------------------------------------------
// LaneAttention: per-lane MLP score -> per-group(8) softmax -> weighted pool
// M = 262144 lanes, groups of 8 contiguous lanes, N = 32768, out [N,192]
//
// R4: 16-col double-buffered cp.async staging (8 chunks, always one prefetch
// in flight), smem ~50 KB -> 4 CTAs/SM (occ ~50%). Phase 2 pools ht/info from
// L2 and fut via ldcs streaming loads.
// ---------------------------------------------------------------------------

static constexpr int TPB = 256;        // threads = rows per block
static constexpr int CS  = 5;          // chunk-buffer row stride in float4 (4 data + 1 pad)
static constexpr int CHUNK_F4 = TPB * CS;            // 1280 float4 per buffer

__device__ __forceinline__ unsigned long long pack_dup(float x) {
    unsigned long long r;
    asm("mov.b64 %0, {%1, %1};" : "=l"(r) : "f"(x));
    return r;
}
__device__ __forceinline__ unsigned long long pack_xy(float x, float y) {
    unsigned long long r;
    asm("mov.b64 %0, {%1, %2};" : "=l"(r) : "f"(x), "f"(y));
    return r;
}
__device__ __forceinline__ void ffma2(unsigned long long &d, unsigned long long a, unsigned long long b) {
    asm("fma.rn.f32x2 %0, %1, %2, %0;" : "+l"(d) : "l"(a), "l"(b));
}
__device__ __forceinline__ float2 unpack2(unsigned long long v) {
    float2 f;
    asm("mov.b64 {%0, %1}, %2;" : "=f"(f.x), "=f"(f.y) : "l"(v));
    return f;
}
__device__ __forceinline__ void cp_async16(uint32_t dst_smem, const void* src) {
    asm volatile("cp.async.cg.shared.global [%0], [%1], 16;\n"
                 :: "r"(dst_smem), "l"(src) : "memory");
}
__device__ __forceinline__ void cp_commit() {
    asm volatile("cp.async.commit_group;\n");
}
template <int N>
__device__ __forceinline__ void cp_wait() {
    asm volatile("cp.async.wait_group %0;\n" :: "n"(N) : "memory");
}

extern __shared__ float smem_f[];
// layout (floats): xbuf 2*1280*4 = 10240 | w1s 2048 | probs 256 | outrow 32 ints
static constexpr int W1S_OFF   = 2 * CHUNK_F4 * 4;    // 10240
static constexpr int SMEM_BYTES = (W1S_OFF + 2048 + 256) * 4 + 128;  // 50304+

// stage 16 columns (4 float4) of all 256 rows of `arr` chunk cc&3 into buffer b
__device__ __forceinline__ void stage_chunk(const float* arr, int row0, int cc,
                                            int b, int tid, uint32_t smem_base)
{
    const float4* src = (const float4*)(arr + (size_t)row0 * 64) + (cc & 3) * 4;
    #pragma unroll
    for (int u = 0; u < 4; ++u) {
        int f = tid + 256 * u;          // flat float4 idx 0..1023
        int r = f >> 2, c = f & 3;
        cp_async16(smem_base + (uint32_t)(b * CHUNK_F4 + r * CS + c) * 16u,
                   src + r * 16 + c);
    }
    cp_commit();
}

__global__ __launch_bounds__(TPB, 4)
void lane_attn_kernel(const float* __restrict__ ht,
                      const float* __restrict__ info,
                      const float* __restrict__ fut,
                      const float* __restrict__ W1,   // [128,16] row-major
                      const float* __restrict__ b1,   // [16]
                      const float* __restrict__ W2,   // [16]
                      const float* __restrict__ b2,   // [1]
                      const int*   __restrict__ seg,  // [M]
                      float* __restrict__ out)        // [N,192]
{
    float*  w1s    = smem_f + W1S_OFF;
    float*  probs  = w1s + 2048;
    int*    outrow = (int*)(probs + TPB);
    const float4* xbuf4 = (const float4*)smem_f;

    const int tid  = threadIdx.x;
    const int row0 = blockIdx.x * TPB;
    const uint32_t xb_s = (uint32_t)__cvta_generic_to_shared(smem_f);

    // kick off the pipeline first so staging overlaps the W1 setup
    stage_chunk(ht, row0, 0, 0, tid, xb_s);
    stage_chunk(ht, row0, 1, 1, tid, xb_s);

    #pragma unroll
    for (int i = 0; i < 8; ++i)
        w1s[tid + i * 256] = W1[tid + i * 256];
    if (tid < 32)
        outrow[tid] = seg[row0 + tid * 8];

    unsigned long long hp[8];
    {
        const float2* b12 = (const float2*)b1;
        #pragma unroll
        for (int j = 0; j < 8; ++j) {
            float2 bv = b12[j];
            hp[j] = pack_xy(bv.x, bv.y);
        }
    }

    // ---- phase 1: 8 chunks (4 ht + 4 info), double-buffered -----------------
    #pragma unroll
    for (int cc = 0; cc < 8; ++cc) {
        if (cc < 7) cp_wait<1>(); else cp_wait<0>();
        __syncthreads();                      // staged data visible to all

        const int b = cc & 1;
        const float4* xb = xbuf4 + b * CHUNK_F4 + tid * CS;
        #pragma unroll
        for (int q2 = 0; q2 < 4; ++q2) {
            float4 v = xb[q2];
            float xs[4] = {v.x, v.y, v.z, v.w};
            #pragma unroll
            for (int c = 0; c < 4; ++c) {
                const int k = cc * 16 + q2 * 4 + c;   // weight row 0..127
                unsigned long long xv = pack_dup(xs[c]);
                const double2* wr = (const double2*)(w1s + k * 16);
                double2 w01 = wr[0];                  // warp-uniform LDS.128
                double2 w23 = wr[1];
                ffma2(hp[0], xv, __double_as_longlong(w01.x));
                ffma2(hp[1], xv, __double_as_longlong(w01.y));
                ffma2(hp[2], xv, __double_as_longlong(w23.x));
                ffma2(hp[3], xv, __double_as_longlong(w23.y));
                double2 w45 = wr[2];
                double2 w67 = wr[3];
                ffma2(hp[4], xv, __double_as_longlong(w45.x));
                ffma2(hp[5], xv, __double_as_longlong(w45.y));
                ffma2(hp[6], xv, __double_as_longlong(w67.x));
                ffma2(hp[7], xv, __double_as_longlong(w67.y));
            }
        }
        __syncthreads();                      // all reads of buffer b done
        if (cc + 2 < 8)                        // refill the buffer just consumed
            stage_chunk(cc + 2 < 4 ? ht : info, row0, cc + 2, b, tid, xb_s);
    }

    // ReLU + second layer -> score
    float score = b2[0];
    #pragma unroll
    for (int j = 0; j < 8; ++j) {
        float2 h2 = unpack2(hp[j]);
        score += fmaxf(h2.x, 0.f) * W2[2 * j]
               + fmaxf(h2.y, 0.f) * W2[2 * j + 1];
    }

    // ---- group-of-8 softmax (warp-aligned groups) ----------------------------
    float m = score;
    #pragma unroll
    for (int d = 1; d < 8; d <<= 1)
        m = fmaxf(m, __shfl_xor_sync(0xffffffffu, m, d));
    float e = __expf(score - m);
    float s = e;
    #pragma unroll
    for (int d = 1; d < 8; d <<= 1)
        s += __shfl_xor_sync(0xffffffffu, s, d);
    probs[tid] = e / s;

    __syncthreads();

    // ---- phase 2: weighted pooling, float4 per lane (ht/info from L2) -------
    const int wrp = tid >> 5;
    const int h   = (tid >> 4) & 1;
    const int k   = tid & 15;

    #pragma unroll
    for (int it = 0; it < 2; ++it) {
        const int gloc  = wrp * 4 + it * 2 + h;          // local group 0..31
        const int lbase = gloc * 8;
        const float4* hb = (const float4*)(ht   + (size_t)(row0 + lbase) * 64);
        const float4* ib = (const float4*)(info + (size_t)(row0 + lbase) * 64);
        const float4* fb = (const float4*)(fut  + (size_t)(row0 + lbase) * 64);

        float4 ah = make_float4(0.f, 0.f, 0.f, 0.f);
        float4 ai = ah, af = ah;
        #pragma unroll
        for (int j = 0; j < 8; ++j) {
            const float p = probs[lbase + j];
            float4 hv = hb[j * 16 + k];                   // L2 hit (phase-1 resident)
            float4 iv = ib[j * 16 + k];                   // L2 hit
            float4 fv = __ldcs(fb + j * 16 + k);          // single-use stream
            ah.x += p * hv.x; ah.y += p * hv.y; ah.z += p * hv.z; ah.w += p * hv.w;
            ai.x += p * iv.x; ai.y += p * iv.y; ai.z += p * iv.z; ai.w += p * iv.w;
            af.x += p * fv.x; af.y += p * fv.y; af.z += p * fv.z; af.w += p * fv.w;
        }
        float4* o4 = (float4*)(out + (size_t)outrow[gloc] * 192);
        o4[k]      = ah;
        o4[16 + k] = ai;
        o4[32 + k] = af;
    }
}

extern "C" void kernel_launch(void* const* d_in, const int* in_sizes, int n_in,
                              void* d_out, int out_size)
{
    const float* ht   = (const float*)d_in[0];
    const float* info = (const float*)d_in[1];
    const float* fut  = (const float*)d_in[2];
    const float* W1   = (const float*)d_in[3];
    const float* b1   = (const float*)d_in[4];
    const float* W2   = (const float*)d_in[5];
    const float* b2   = (const float*)d_in[6];
    const int*   seg  = (const int*)d_in[7];
    float* out = (float*)d_out;

    const int M = in_sizes[0] / 64;          // 262144
    const int nblocks = M / TPB;             // 1024

    static bool attr_set = false;
    if (!attr_set) {
        cudaFuncSetAttribute(lane_attn_kernel,
                             cudaFuncAttributeMaxDynamicSharedMemorySize, SMEM_BYTES);
        attr_set = true;
    }

    lane_attn_kernel<<<nblocks, TPB, SMEM_BYTES>>>(ht, info, fut, W1, b1, W2, b2, seg, out);
}

// round 5
// speedup vs baseline: 1.8974x; 1.2821x over previous
#include <cuda_runtime.h>
#include <cstdint>

// ---------------------------------------------------------------------------
// LaneAttention: per-lane MLP score -> per-group(8) softmax -> weighted pool
// M = 262144 lanes, groups of 8 contiguous lanes, N = 32768, out [N,192]
//
// R5: W1 lives in __constant__ memory (copied in with one async D2D memcpy
// node). Weight reads become immediate-addressed constant-port loads (LDC/
// LDCU) instead of 512 LDS.128/thread on the L1 port. x staging pipeline and
// float4 phase-2 pooling unchanged from R4.
// ---------------------------------------------------------------------------

static constexpr int TPB = 256;        // threads = rows per block
static constexpr int CS  = 5;          // chunk-buffer row stride in float4 (4 data + 1 pad)
static constexpr int CHUNK_F4 = TPB * CS;            // 1280 float4 per buffer

__constant__ float cW1[128 * 16];      // 8 KB, fits the constant bank

__device__ __forceinline__ unsigned long long pack_dup(float x) {
    unsigned long long r;
    asm("mov.b64 %0, {%1, %1};" : "=l"(r) : "f"(x));
    return r;
}
__device__ __forceinline__ unsigned long long pack_xy(float x, float y) {
    unsigned long long r;
    asm("mov.b64 %0, {%1, %2};" : "=l"(r) : "f"(x), "f"(y));
    return r;
}
__device__ __forceinline__ void ffma2(unsigned long long &d, unsigned long long a, unsigned long long b) {
    asm("fma.rn.f32x2 %0, %1, %2, %0;" : "+l"(d) : "l"(a), "l"(b));
}
__device__ __forceinline__ float2 unpack2(unsigned long long v) {
    float2 f;
    asm("mov.b64 {%0, %1}, %2;" : "=f"(f.x), "=f"(f.y) : "l"(v));
    return f;
}
__device__ __forceinline__ void cp_async16(uint32_t dst_smem, const void* src) {
    asm volatile("cp.async.cg.shared.global [%0], [%1], 16;\n"
                 :: "r"(dst_smem), "l"(src) : "memory");
}
__device__ __forceinline__ void cp_commit() {
    asm volatile("cp.async.commit_group;\n");
}
template <int N>
__device__ __forceinline__ void cp_wait() {
    asm volatile("cp.async.wait_group %0;\n" :: "n"(N) : "memory");
}

extern __shared__ float smem_f[];
// layout (floats): xbuf 2*1280*4 = 10240 | probs 256 | outrow 32 ints
static constexpr int PROBS_OFF  = 2 * CHUNK_F4 * 4;                 // 10240
static constexpr int SMEM_BYTES = (PROBS_OFF + 256) * 4 + 128;      // ~42.1 KB

// stage 16 columns (4 float4) of all 256 rows of `arr` chunk cc&3 into buffer b
__device__ __forceinline__ void stage_chunk(const float* arr, int row0, int cc,
                                            int b, int tid, uint32_t smem_base)
{
    const float4* src = (const float4*)(arr + (size_t)row0 * 64) + (cc & 3) * 4;
    #pragma unroll
    for (int u = 0; u < 4; ++u) {
        int f = tid + 256 * u;          // flat float4 idx 0..1023
        int r = f >> 2, c = f & 3;
        cp_async16(smem_base + (uint32_t)(b * CHUNK_F4 + r * CS + c) * 16u,
                   src + r * 16 + c);
    }
    cp_commit();
}

__global__ __launch_bounds__(TPB, 4)
void lane_attn_kernel(const float* __restrict__ ht,
                      const float* __restrict__ info,
                      const float* __restrict__ fut,
                      const float* __restrict__ b1,   // [16]
                      const float* __restrict__ W2,   // [16]
                      const float* __restrict__ b2,   // [1]
                      const int*   __restrict__ seg,  // [M]
                      float* __restrict__ out)        // [N,192]
{
    float*  probs  = smem_f + PROBS_OFF;
    int*    outrow = (int*)(probs + TPB);
    const float4* xbuf4 = (const float4*)smem_f;

    const int tid  = threadIdx.x;
    const int row0 = blockIdx.x * TPB;
    const uint32_t xb_s = (uint32_t)__cvta_generic_to_shared(smem_f);

    // kick off the pipeline immediately
    stage_chunk(ht, row0, 0, 0, tid, xb_s);
    stage_chunk(ht, row0, 1, 1, tid, xb_s);

    if (tid < 32)
        outrow[tid] = seg[row0 + tid * 8];

    unsigned long long hp[8];
    {
        const float2* b12 = (const float2*)b1;
        #pragma unroll
        for (int j = 0; j < 8; ++j) {
            float2 bv = b12[j];
            hp[j] = pack_xy(bv.x, bv.y);
        }
    }

    // ---- phase 1: 8 chunks (4 ht + 4 info), double-buffered ------------------
    #pragma unroll
    for (int cc = 0; cc < 8; ++cc) {
        if (cc < 7) cp_wait<1>(); else cp_wait<0>();
        __syncthreads();                      // staged data visible to all

        const int b = cc & 1;
        const float4* xb = xbuf4 + b * CHUNK_F4 + tid * CS;
        #pragma unroll
        for (int q2 = 0; q2 < 4; ++q2) {
            float4 v = xb[q2];
            float xs[4] = {v.x, v.y, v.z, v.w};
            #pragma unroll
            for (int c = 0; c < 4; ++c) {
                const int k = cc * 16 + q2 * 4 + c;   // weight row, compile-time
                unsigned long long xv = pack_dup(xs[c]);
                // constant-port loads: immediate address, uniform across warp
                const double2* wr = (const double2*)(cW1 + k * 16);
                double2 w01 = wr[0];
                double2 w23 = wr[1];
                ffma2(hp[0], xv, __double_as_longlong(w01.x));
                ffma2(hp[1], xv, __double_as_longlong(w01.y));
                ffma2(hp[2], xv, __double_as_longlong(w23.x));
                ffma2(hp[3], xv, __double_as_longlong(w23.y));
                double2 w45 = wr[2];
                double2 w67 = wr[3];
                ffma2(hp[4], xv, __double_as_longlong(w45.x));
                ffma2(hp[5], xv, __double_as_longlong(w45.y));
                ffma2(hp[6], xv, __double_as_longlong(w67.x));
                ffma2(hp[7], xv, __double_as_longlong(w67.y));
            }
        }
        __syncthreads();                      // all reads of buffer b done
        if (cc + 2 < 8)                        // refill the buffer just consumed
            stage_chunk(cc + 2 < 4 ? ht : info, row0, cc + 2, b, tid, xb_s);
    }

    // ReLU + second layer -> score
    float score = b2[0];
    #pragma unroll
    for (int j = 0; j < 8; ++j) {
        float2 h2 = unpack2(hp[j]);
        score += fmaxf(h2.x, 0.f) * W2[2 * j]
               + fmaxf(h2.y, 0.f) * W2[2 * j + 1];
    }

    // ---- group-of-8 softmax (warp-aligned groups) -----------------------------
    float m = score;
    #pragma unroll
    for (int d = 1; d < 8; d <<= 1)
        m = fmaxf(m, __shfl_xor_sync(0xffffffffu, m, d));
    float e = __expf(score - m);
    float s = e;
    #pragma unroll
    for (int d = 1; d < 8; d <<= 1)
        s += __shfl_xor_sync(0xffffffffu, s, d);
    probs[tid] = e / s;

    __syncthreads();

    // ---- phase 2: weighted pooling, float4 per lane (ht/info from L2) --------
    const int wrp = tid >> 5;
    const int h   = (tid >> 4) & 1;
    const int k   = tid & 15;

    #pragma unroll
    for (int it = 0; it < 2; ++it) {
        const int gloc  = wrp * 4 + it * 2 + h;          // local group 0..31
        const int lbase = gloc * 8;
        const float4* hb = (const float4*)(ht   + (size_t)(row0 + lbase) * 64);
        const float4* ib = (const float4*)(info + (size_t)(row0 + lbase) * 64);
        const float4* fb = (const float4*)(fut  + (size_t)(row0 + lbase) * 64);

        float4 ah = make_float4(0.f, 0.f, 0.f, 0.f);
        float4 ai = ah, af = ah;
        #pragma unroll
        for (int j = 0; j < 8; ++j) {
            const float p = probs[lbase + j];
            float4 hv = hb[j * 16 + k];                   // L2 hit (phase-1 resident)
            float4 iv = ib[j * 16 + k];                   // L2 hit
            float4 fv = __ldcs(fb + j * 16 + k);          // single-use stream
            ah.x += p * hv.x; ah.y += p * hv.y; ah.z += p * hv.z; ah.w += p * hv.w;
            ai.x += p * iv.x; ai.y += p * iv.y; ai.z += p * iv.z; ai.w += p * iv.w;
            af.x += p * fv.x; af.y += p * fv.y; af.z += p * fv.z; af.w += p * fv.w;
        }
        float4* o4 = (float4*)(out + (size_t)outrow[gloc] * 192);
        o4[k]      = ah;
        o4[16 + k] = ai;
        o4[32 + k] = af;
    }
}

extern "C" void kernel_launch(void* const* d_in, const int* in_sizes, int n_in,
                              void* d_out, int out_size)
{
    const float* ht   = (const float*)d_in[0];
    const float* info = (const float*)d_in[1];
    const float* fut  = (const float*)d_in[2];
    const float* W1   = (const float*)d_in[3];
    const float* b1   = (const float*)d_in[4];
    const float* W2   = (const float*)d_in[5];
    const float* b2   = (const float*)d_in[6];
    const int*   seg  = (const int*)d_in[7];
    float* out = (float*)d_out;

    const int M = in_sizes[0] / 64;          // 262144
    const int nblocks = M / TPB;             // 1024

    static void* cw1_addr = nullptr;         // host-side cache of symbol addr (no stream op)
    if (!cw1_addr) {
        cudaGetSymbolAddress(&cw1_addr, cW1);
        cudaFuncSetAttribute(lane_attn_kernel,
                             cudaFuncAttributeMaxDynamicSharedMemorySize, SMEM_BYTES);
    }

    // D2D async copy into constant bank — a single graph memcpy node
    cudaMemcpyAsync(cw1_addr, W1, 128 * 16 * sizeof(float), cudaMemcpyDeviceToDevice);

    lane_attn_kernel<<<nblocks, TPB, SMEM_BYTES>>>(ht, info, fut, b1, W2, b2, seg, out);
}